// round 6
// baseline (speedup 1.0000x reference)
#include <cuda_runtime.h>
#include <cuda_bf16.h>
#include <mma.h>
#include <math.h>
#include <stdint.h>

using namespace nvcuda;

#define B_   4
#define S_   256
#define V_   64
#define LP1_ 11
#define H_   128
#define NH_  8
#define DH_  16
#define NL_  3
#define M_   (B_*S_)   // 1024

// ---------------- scratch (device globals; no allocation) ----------------
__device__ float g_adjT[V_*LP1_*V_];
__device__ float g_z [M_*V_*H_];
__device__ float g_z2[M_*V_*H_];
__device__ float g_qkv[3*M_*V_*H_];

// ---------------- stage 0: sigmoid + transpose of adjacency --------------
__global__ void prep_adj_kernel(const float* __restrict__ logits, float* __restrict__ adjT) {
    int idx = blockIdx.x * 256 + threadIdx.x;
    if (idx >= V_*V_*LP1_) return;
    int s = idx % V_;
    int r = idx / V_;
    int l = r % LP1_;
    int i = r / LP1_;
    float x = logits[(s*V_ + i)*LP1_ + l];
    adjT[idx] = 1.f / (1.f + __expf(-x));
}

// ---------------- stage 1: z[b,t,i,h] -------------------------------------
__global__ __launch_bounds__(256)
void stage1_kernel(const float* __restrict__ x, const float* __restrict__ adjT,
                   const float* __restrict__ var_emb, const float* __restrict__ temp_emb,
                   float* __restrict__ z) {
    int bt = blockIdx.x;
    int b = bt >> 8;
    int t = bt & 255;
    __shared__ float xw[LP1_][V_];
    __shared__ float Am[V_][V_ + 1];
    __shared__ float Bls[V_][LP1_ + 1];
    int tid = threadIdx.x;

    for (int p = tid; p < LP1_*V_; p += 256) {
        int l = p / V_, s = p % V_;
        int tt = t - l;
        xw[l][s] = (tt >= 0) ? x[((size_t)(b*S_ + tt))*V_ + s] : 0.f;
    }
    __syncthreads();

    for (int p = tid; p < V_*V_; p += 256) {
        int i = p >> 6, s = p & 63;
        const float* ap = adjT + (size_t)i*LP1_*V_ + s;
        float a = 0.f;
        #pragma unroll
        for (int l = 0; l < LP1_; l++) a += xw[l][s] * ap[l*V_];
        Am[i][s] = a;
    }
    for (int p = tid; p < V_*LP1_; p += 256) {
        int i = p / LP1_, l = p % LP1_;
        const float* ap = adjT + ((size_t)i*LP1_ + l)*V_;
        float a = 0.f;
        #pragma unroll 8
        for (int s = 0; s < V_; s++) a += xw[l][s] * ap[s];
        Bls[i][l] = a;
    }
    __syncthreads();

    int tx = tid & 15, ty = tid >> 4;
    float acc[4][8];
    #pragma unroll
    for (int r = 0; r < 4; r++)
        #pragma unroll
        for (int c = 0; c < 8; c++) acc[r][c] = 0.f;

    for (int s = 0; s < V_; s++) {
        float a0 = Am[ty*4+0][s], a1 = Am[ty*4+1][s], a2 = Am[ty*4+2][s], a3 = Am[ty*4+3][s];
        const float4* vp = (const float4*)(var_emb + (size_t)s*H_ + tx*8);
        float4 v0 = vp[0], v1 = vp[1];
        float bv[8] = {v0.x,v0.y,v0.z,v0.w,v1.x,v1.y,v1.z,v1.w};
        #pragma unroll
        for (int c = 0; c < 8; c++) {
            acc[0][c] += a0*bv[c]; acc[1][c] += a1*bv[c];
            acc[2][c] += a2*bv[c]; acc[3][c] += a3*bv[c];
        }
    }
    #pragma unroll
    for (int l = 0; l < LP1_; l++) {
        float a0 = Bls[ty*4+0][l], a1 = Bls[ty*4+1][l], a2 = Bls[ty*4+2][l], a3 = Bls[ty*4+3][l];
        const float4* vp = (const float4*)(temp_emb + (size_t)l*H_ + tx*8);
        float4 v0 = vp[0], v1 = vp[1];
        float bv[8] = {v0.x,v0.y,v0.z,v0.w,v1.x,v1.y,v1.z,v1.w};
        #pragma unroll
        for (int c = 0; c < 8; c++) {
            acc[0][c] += a0*bv[c]; acc[1][c] += a1*bv[c];
            acc[2][c] += a2*bv[c]; acc[3][c] += a3*bv[c];
        }
    }
    #pragma unroll
    for (int r = 0; r < 4; r++) {
        int i = ty*4 + r;
        float* zp = z + ((size_t)bt*V_ + i)*H_ + tx*8;
        *(float4*)(zp)   = make_float4(acc[r][0], acc[r][1], acc[r][2], acc[r][3]);
        *(float4*)(zp+4) = make_float4(acc[r][4], acc[r][5], acc[r][6], acc[r][7]);
    }
}

// ============= wmma bf16-split per-variable GEMM (fp32-accurate) ===========
// K-chunked (2 chunks of 64) so tiles fit 70KB -> 2 CTAs/SM.
#define OFF_P0   0        // bias (512B)
#define OFF_P1   512      // ln gamma / head weight
#define OFF_P2   1024     // ln beta
#define OFF_T    2048
#define LDA      72       // bf16 per A-chunk row (64+8)
#define LDB      136      // bf16 per B-chunk row (128+8)
#define A_TILE_B (128*LDA*2)   // 18432
#define B_TILE_B (64*LDB*2)    // 17408
#define OFF_AHI  (OFF_T)
#define OFF_ALO  (OFF_AHI + A_TILE_B)
#define OFF_BHI  (OFF_ALO + A_TILE_B)
#define OFF_BLO  (OFF_BHI + B_TILE_B)
#define GSM_TOTAL (OFF_BLO + B_TILE_B)   // 73728 B
#define OFF_C    OFF_T                   // fp32 C overlaps tiles post-mma
#define LDC      132

__device__ __forceinline__ uint32_t pack_hi(float a, float b) {
    __nv_bfloat16 ha = __float2bfloat16(a), hb = __float2bfloat16(b);
    return ((uint32_t)__bfloat16_as_ushort(hb) << 16) | __bfloat16_as_ushort(ha);
}
__device__ __forceinline__ uint32_t pack_lo(float a, float b) {
    __nv_bfloat16 ha = __float2bfloat16(a), hb = __float2bfloat16(b);
    float ra = a - __bfloat162float(ha), rb = b - __bfloat162float(hb);
    __nv_bfloat16 la = __float2bfloat16(ra), lb = __float2bfloat16(rb);
    return ((uint32_t)__bfloat16_as_ushort(lb) << 16) | __bfloat16_as_ushort(la);
}

// A chunk: 128 rows x 64 k
__device__ __forceinline__ void fill_A(char* smem, const float* __restrict__ src,
                                       size_t rstride, int kofs, int tid) {
    #pragma unroll
    for (int i = 0; i < 8; i++) {
        int f = tid + 256*i;
        int row = f >> 4, c4 = (f & 15) * 4;
        float4 vv = *(const float4*)(src + (size_t)row*rstride + kofs + c4);
        uint2 hv, lv;
        hv.x = pack_hi(vv.x, vv.y); hv.y = pack_hi(vv.z, vv.w);
        lv.x = pack_lo(vv.x, vv.y); lv.y = pack_lo(vv.z, vv.w);
        uint32_t boff = (uint32_t)row*(LDA*2) + (uint32_t)c4*2;
        *(uint2*)(smem + OFF_AHI + boff) = hv;
        *(uint2*)(smem + OFF_ALO + boff) = lv;
    }
}
// B chunk: 64 k-rows x 128 n  (weights k-major: W[k][n])
__device__ __forceinline__ void fill_B(char* smem, const float* __restrict__ src,
                                       int kofs, int tid) {
    #pragma unroll
    for (int i = 0; i < 8; i++) {
        int f = tid + 256*i;
        int row = f >> 5, c4 = (f & 31) * 4;
        float4 vv = *(const float4*)(src + (size_t)(kofs + row)*H_ + c4);
        uint2 hv, lv;
        hv.x = pack_hi(vv.x, vv.y); hv.y = pack_hi(vv.z, vv.w);
        lv.x = pack_lo(vv.x, vv.y); lv.y = pack_lo(vv.z, vv.w);
        uint32_t boff = (uint32_t)row*(LDB*2) + (uint32_t)c4*2;
        *(uint2*)(smem + OFF_BHI + boff) = hv;
        *(uint2*)(smem + OFF_BLO + boff) = lv;
    }
}

// MODE 0: out = D              (QKV via blockIdx.z; bias folded into attn)
// MODE 1: out = GELU(LN(D + bias)*g + b)
// MODE 2: out[m,v] = (D + bias) . oW + oB
template <int MODE>
__global__ __launch_bounds__(256, 2)
void vgemm_wmma(const float* __restrict__ A, const float* __restrict__ W,
                const float* __restrict__ b0, const float* __restrict__ W1,
                const float* __restrict__ W2,
                const float* __restrict__ lng, const float* __restrict__ lnb,
                const float* __restrict__ oW, const float* __restrict__ oB,
                float* __restrict__ out, int w_vs, int b_vs) {
    extern __shared__ char smem[];
    int tid = threadIdx.x;
    int v = blockIdx.y, m0 = blockIdx.x * 128;

    if (MODE == 0) {
        int zi = blockIdx.z;
        if (zi == 1) W = W1;
        else if (zi == 2) W = W2;
        out += (size_t)zi * M_ * V_ * H_;
    }

    float* sBias = (float*)(smem + OFF_P0);
    float* sG    = (float*)(smem + OFF_P1);
    float* sBeta = (float*)(smem + OFF_P2);
    if (MODE != 0 && tid < 128) {
        sBias[tid] = b0[(size_t)v*b_vs + tid];
        if (MODE == 1) {
            sG[tid]    = lng[(size_t)v*b_vs + tid];
            sBeta[tid] = lnb[(size_t)v*b_vs + tid];
        } else {
            sG[tid] = oW[(size_t)v*H_ + tid];
        }
    }

    int w = tid >> 5;
    int wm = w & 3;        // 4 warps over M (32 rows)
    int wn = w >> 2;       // 2 warps over N (64 cols)

    wmma::fragment<wmma::accumulator, 16, 16, 16, float> acc[2][4];
    #pragma unroll
    for (int mi = 0; mi < 2; mi++)
        #pragma unroll
        for (int ni = 0; ni < 4; ni++) wmma::fill_fragment(acc[mi][ni], 0.f);

    const __nv_bfloat16* aHi = (const __nv_bfloat16*)(smem + OFF_AHI);
    const __nv_bfloat16* aLo = (const __nv_bfloat16*)(smem + OFF_ALO);
    const __nv_bfloat16* bHi = (const __nv_bfloat16*)(smem + OFF_BHI);
    const __nv_bfloat16* bLo = (const __nv_bfloat16*)(smem + OFF_BLO);

    const float* Asrc = A + ((size_t)m0*V_ + v)*H_;
    const float* Wsrc = W + (size_t)v*w_vs;

    #pragma unroll
    for (int ch = 0; ch < 2; ch++) {
        if (ch) __syncthreads();   // tiles free before overwrite
        fill_A(smem, Asrc, (size_t)V_*H_, ch*64, tid);
        fill_B(smem, Wsrc, ch*64, tid);
        __syncthreads();
        #pragma unroll
        for (int p = 0; p < 3; p++) {
            const __nv_bfloat16* aS = (p == 2) ? aLo : aHi;
            const __nv_bfloat16* bS = (p == 1) ? bLo : bHi;
            #pragma unroll
            for (int k0 = 0; k0 < 4; k0++) {
                int k = k0 * 16;
                wmma::fragment<wmma::matrix_a, 16, 16, 16, __nv_bfloat16, wmma::row_major> af[2];
                wmma::fragment<wmma::matrix_b, 16, 16, 16, __nv_bfloat16, wmma::row_major> bf[4];
                #pragma unroll
                for (int mi = 0; mi < 2; mi++)
                    wmma::load_matrix_sync(af[mi], aS + (size_t)(wm*32 + mi*16)*LDA + k, LDA);
                #pragma unroll
                for (int ni = 0; ni < 4; ni++)
                    wmma::load_matrix_sync(bf[ni], bS + (size_t)k*LDB + wn*64 + ni*16, LDB);
                #pragma unroll
                for (int mi = 0; mi < 2; mi++)
                    #pragma unroll
                    for (int ni = 0; ni < 4; ni++)
                        wmma::mma_sync(acc[mi][ni], af[mi], bf[ni], acc[mi][ni]);
            }
        }
    }

    if constexpr (MODE == 0) {
        // direct fragment -> gmem store (row stride V*H)
        #pragma unroll
        for (int mi = 0; mi < 2; mi++)
            #pragma unroll
            for (int ni = 0; ni < 4; ni++)
                wmma::store_matrix_sync(
                    out + ((size_t)(m0 + wm*32 + mi*16)*V_ + v)*H_ + wn*64 + ni*16,
                    acc[mi][ni], (unsigned)(V_*H_), wmma::mem_row_major);
        return;
    }

    __syncthreads();   // done reading tiles; reuse region as fp32 C
    float* Cs = (float*)(smem + OFF_C);
    #pragma unroll
    for (int mi = 0; mi < 2; mi++)
        #pragma unroll
        for (int ni = 0; ni < 4; ni++)
            wmma::store_matrix_sync(Cs + (size_t)(wm*32 + mi*16)*LDC + wn*64 + ni*16,
                                    acc[mi][ni], LDC, wmma::mem_row_major);
    __syncthreads();

    // ---- epilogue: thread owns half a row (64 cols); partner = lane^1 ----
    int r2 = tid >> 1, half = tid & 1;
    const float* crow = Cs + (size_t)r2*LDC + half*64;
    const float* bcol = sBias + half*64;
    int grow = m0 + r2;

    if constexpr (MODE == 1) {
        float s = 0.f, q = 0.f;
        #pragma unroll
        for (int c = 0; c < 64; c += 4) {
            float4 cc = *(const float4*)(crow + c);
            float4 bb = *(const float4*)(bcol + c);
            float y0 = cc.x + bb.x, y1 = cc.y + bb.y, y2 = cc.z + bb.z, y3 = cc.w + bb.w;
            s += y0 + y1 + y2 + y3;
            q += y0*y0 + y1*y1 + y2*y2 + y3*y3;
        }
        s += __shfl_xor_sync(0xFFFFFFFFu, s, 1);
        q += __shfl_xor_sync(0xFFFFFFFFu, q, 1);
        float mean = s * (1.f/128.f);
        float var  = q * (1.f/128.f) - mean*mean;
        float rstd = rsqrtf(var + 1e-5f);
        float* orow = out + ((size_t)grow*V_ + v)*H_ + half*64;
        const float* gcol = sG + half*64;
        const float* lcol = sBeta + half*64;
        #pragma unroll
        for (int c = 0; c < 64; c += 4) {
            float4 cc = *(const float4*)(crow + c);
            float4 bb = *(const float4*)(bcol + c);
            float4 gg = *(const float4*)(gcol + c);
            float4 ll = *(const float4*)(lcol + c);
            float yv[4] = {cc.x+bb.x, cc.y+bb.y, cc.z+bb.z, cc.w+bb.w};
            float gv[4] = {gg.x, gg.y, gg.z, gg.w};
            float lv[4] = {ll.x, ll.y, ll.z, ll.w};
            float o4[4];
            #pragma unroll
            for (int j = 0; j < 4; j++) {
                float t2 = (yv[j] - mean) * rstd * gv[j] + lv[j];
                o4[j] = 0.5f * t2 * (1.f + erff(t2 * 0.7071067811865476f));
            }
            *(float4*)(orow + c) = make_float4(o4[0], o4[1], o4[2], o4[3]);
        }
    } else {  // MODE 2
        const float* gcol = sG + half*64;
        float p = 0.f;
        #pragma unroll
        for (int c = 0; c < 64; c += 4) {
            float4 cc = *(const float4*)(crow + c);
            float4 bb = *(const float4*)(bcol + c);
            float4 gg = *(const float4*)(gcol + c);
            p += (cc.x+bb.x)*gg.x + (cc.y+bb.y)*gg.y + (cc.z+bb.z)*gg.z + (cc.w+bb.w)*gg.w;
        }
        p += __shfl_xor_sync(0xFFFFFFFFu, p, 1);
        if (half == 0)
            out[(size_t)grow*V_ + v] = p + oB[v];
    }
}

// ---------------- attention (adds q/k/v biases): block per (b,v,head) -----
__global__ __launch_bounds__(256)
void attn_kernel(const float* __restrict__ qkv,
                 const float* __restrict__ bq, const float* __restrict__ bk,
                 const float* __restrict__ bv, float* __restrict__ o) {
    int bid = blockIdx.x;
    int n = bid & 7;
    int v = (bid >> 3) & 63;
    int b = bid >> 9;
    __shared__ float Ks[S_][DH_];
    __shared__ float Vs[S_][DH_];
    int t = threadIdx.x;

    const float* q  = qkv;
    const float* k  = qkv + (size_t)M_*V_*H_;
    const float* vv = qkv + (size_t)2*M_*V_*H_;

    size_t rowstride = (size_t)V_ * H_;
    size_t base = ((size_t)(b*S_)*V_ + v)*H_ + n*DH_;
    size_t bofs = (size_t)v*H_ + n*DH_;

    float4 bk0 = *(const float4*)(bk + bofs),     bk1 = *(const float4*)(bk + bofs + 4);
    float4 bk2 = *(const float4*)(bk + bofs + 8), bk3 = *(const float4*)(bk + bofs + 12);
    float4 bv0 = *(const float4*)(bv + bofs),     bv1 = *(const float4*)(bv + bofs + 4);
    float4 bv2 = *(const float4*)(bv + bofs + 8), bv3 = *(const float4*)(bv + bofs + 12);
    {
        const float4* kp = (const float4*)(k  + base + (size_t)t*rowstride);
        const float4* vp = (const float4*)(vv + base + (size_t)t*rowstride);
        float4 k0 = kp[0], k1 = kp[1], k2 = kp[2], k3 = kp[3];
        float4 w0 = vp[0], w1 = vp[1], w2 = vp[2], w3 = vp[3];
        k0.x+=bk0.x; k0.y+=bk0.y; k0.z+=bk0.z; k0.w+=bk0.w;
        k1.x+=bk1.x; k1.y+=bk1.y; k1.z+=bk1.z; k1.w+=bk1.w;
        k2.x+=bk2.x; k2.y+=bk2.y; k2.z+=bk2.z; k2.w+=bk2.w;
        k3.x+=bk3.x; k3.y+=bk3.y; k3.z+=bk3.z; k3.w+=bk3.w;
        w0.x+=bv0.x; w0.y+=bv0.y; w0.z+=bv0.z; w0.w+=bv0.w;
        w1.x+=bv1.x; w1.y+=bv1.y; w1.z+=bv1.z; w1.w+=bv1.w;
        w2.x+=bv2.x; w2.y+=bv2.y; w2.z+=bv2.z; w2.w+=bv2.w;
        w3.x+=bv3.x; w3.y+=bv3.y; w3.z+=bv3.z; w3.w+=bv3.w;
        *(float4*)&Ks[t][0]  = k0; *(float4*)&Ks[t][4]  = k1;
        *(float4*)&Ks[t][8]  = k2; *(float4*)&Ks[t][12] = k3;
        *(float4*)&Vs[t][0]  = w0; *(float4*)&Vs[t][4]  = w1;
        *(float4*)&Vs[t][8]  = w2; *(float4*)&Vs[t][12] = w3;
    }
    float4 q0, q1, q2, q3;
    {
        const float4* qp = (const float4*)(q + base + (size_t)t*rowstride);
        float4 a0 = *(const float4*)(bq + bofs),     a1 = *(const float4*)(bq + bofs + 4);
        float4 a2 = *(const float4*)(bq + bofs + 8), a3 = *(const float4*)(bq + bofs + 12);
        q0 = qp[0]; q1 = qp[1]; q2 = qp[2]; q3 = qp[3];
        q0.x+=a0.x; q0.y+=a0.y; q0.z+=a0.z; q0.w+=a0.w;
        q1.x+=a1.x; q1.y+=a1.y; q1.z+=a1.z; q1.w+=a1.w;
        q2.x+=a2.x; q2.y+=a2.y; q2.z+=a2.z; q2.w+=a2.w;
        q3.x+=a3.x; q3.y+=a3.y; q3.z+=a3.z; q3.w+=a3.w;
    }
    __syncthreads();

    float m = -1e30f, ssum = 0.f;
    float av[16];
    #pragma unroll
    for (int d = 0; d < 16; d++) av[d] = 0.f;

    for (int j = 0; j < S_; j++) {
        float4 k0 = *(float4*)&Ks[j][0],  k1 = *(float4*)&Ks[j][4];
        float4 k2 = *(float4*)&Ks[j][8],  k3 = *(float4*)&Ks[j][12];
        float s = q0.x*k0.x + q0.y*k0.y + q0.z*k0.z + q0.w*k0.w
                + q1.x*k1.x + q1.y*k1.y + q1.z*k1.z + q1.w*k1.w
                + q2.x*k2.x + q2.y*k2.y + q2.z*k2.z + q2.w*k2.w
                + q3.x*k3.x + q3.y*k3.y + q3.z*k3.z + q3.w*k3.w;
        s *= 0.25f;
        if (s > m) {
            float corr = __expf(m - s);
            ssum *= corr;
            #pragma unroll
            for (int d = 0; d < 16; d++) av[d] *= corr;
            m = s;
        }
        float e = __expf(s - m);
        ssum += e;
        float4 w0 = *(float4*)&Vs[j][0],  w1 = *(float4*)&Vs[j][4];
        float4 w2 = *(float4*)&Vs[j][8],  w3 = *(float4*)&Vs[j][12];
        av[0]  += e*w0.x; av[1]  += e*w0.y; av[2]  += e*w0.z; av[3]  += e*w0.w;
        av[4]  += e*w1.x; av[5]  += e*w1.y; av[6]  += e*w1.z; av[7]  += e*w1.w;
        av[8]  += e*w2.x; av[9]  += e*w2.y; av[10] += e*w2.z; av[11] += e*w2.w;
        av[12] += e*w3.x; av[13] += e*w3.y; av[14] += e*w3.z; av[15] += e*w3.w;
    }
    float inv = 1.f / ssum;
    float* op = o + base + (size_t)t*rowstride;
    *(float4*)(op)    = make_float4(av[0]*inv,  av[1]*inv,  av[2]*inv,  av[3]*inv);
    *(float4*)(op+4)  = make_float4(av[4]*inv,  av[5]*inv,  av[6]*inv,  av[7]*inv);
    *(float4*)(op+8)  = make_float4(av[8]*inv,  av[9]*inv,  av[10]*inv, av[11]*inv);
    *(float4*)(op+12) = make_float4(av[12]*inv, av[13]*inv, av[14]*inv, av[15]*inv);
}

// ---------------- launch ---------------------------------------------------
extern "C" void kernel_launch(void* const* d_in, const int* in_sizes, int n_in,
                              void* d_out, int out_size) {
    const float* x       = (const float*)d_in[0];
    const float* adjlog  = (const float*)d_in[1];
    const float* var_emb = (const float*)d_in[2];
    const float* temp_emb= (const float*)d_in[3];
    const float* mech_W  = (const float*)d_in[4];
    const float* mech_b  = (const float*)d_in[5];
    const float* ln_g    = (const float*)d_in[6];
    const float* ln_b    = (const float*)d_in[7];
    const float* Wq      = (const float*)d_in[8];
    const float* Wk      = (const float*)d_in[9];
    const float* Wv      = (const float*)d_in[10];
    const float* Wo      = (const float*)d_in[11];
    const float* bq      = (const float*)d_in[12];
    const float* bk      = (const float*)d_in[13];
    const float* bv      = (const float*)d_in[14];
    const float* bo      = (const float*)d_in[15];
    const float* out_W   = (const float*)d_in[16];
    const float* out_b   = (const float*)d_in[17];
    float* out = (float*)d_out;

    float *adjT, *z, *z2, *qkv;
    cudaGetSymbolAddress((void**)&adjT, g_adjT);
    cudaGetSymbolAddress((void**)&z,    g_z);
    cudaGetSymbolAddress((void**)&z2,   g_z2);
    cudaGetSymbolAddress((void**)&qkv,  g_qkv);

    cudaFuncSetAttribute(vgemm_wmma<0>, cudaFuncAttributeMaxDynamicSharedMemorySize, GSM_TOTAL);
    cudaFuncSetAttribute(vgemm_wmma<1>, cudaFuncAttributeMaxDynamicSharedMemorySize, GSM_TOTAL);
    cudaFuncSetAttribute(vgemm_wmma<2>, cudaFuncAttributeMaxDynamicSharedMemorySize, GSM_TOTAL);

    prep_adj_kernel<<<(V_*V_*LP1_ + 255)/256, 256>>>(adjlog, adjT);
    stage1_kernel<<<M_, 256>>>(x, adjT, var_emb, temp_emb, z);

    dim3 gg(M_/128, V_);
    vgemm_wmma<1><<<gg, 256, GSM_TOTAL>>>(z,  mech_W + 0*H_*H_, mech_b + 0*H_,
                                          nullptr, nullptr,
                                          ln_g + 0*H_, ln_b + 0*H_, nullptr, nullptr,
                                          z2, NL_*H_*H_, NL_*H_);
    vgemm_wmma<1><<<gg, 256, GSM_TOTAL>>>(z2, mech_W + 1*H_*H_, mech_b + 1*H_,
                                          nullptr, nullptr,
                                          ln_g + 1*H_, ln_b + 1*H_, nullptr, nullptr,
                                          z,  NL_*H_*H_, NL_*H_);
    vgemm_wmma<1><<<gg, 256, GSM_TOTAL>>>(z,  mech_W + 2*H_*H_, mech_b + 2*H_,
                                          nullptr, nullptr,
                                          ln_g + 2*H_, ln_b + 2*H_, nullptr, nullptr,
                                          z2, NL_*H_*H_, NL_*H_);
    // fused QKV (grid.z selects weight/output; biases applied in attn)
    dim3 gq(M_/128, V_, 3);
    vgemm_wmma<0><<<gq, 256, GSM_TOTAL>>>(z2, Wq, nullptr, Wk, Wv,
                                          nullptr, nullptr, nullptr, nullptr,
                                          qkv, H_*H_, H_);
    attn_kernel<<<B_*V_*NH_, 256>>>(qkv, bq, bk, bv, z);
    // O-proj + output head fused
    vgemm_wmma<2><<<gg, 256, GSM_TOTAL>>>(z, Wo, bo, nullptr, nullptr,
                                          nullptr, nullptr, out_W, out_b, out, H_*H_, H_);
}